// round 14
// baseline (speedup 1.0000x reference)
#include <cuda_runtime.h>
#include <cuda_bf16.h>
#include <math.h>

#define NROWS 8000
#define NV4   2000
#define D     256
#define P     128
#define CAP   192       // max deg ~95 << 192
#define NTRI  4000      // paired-row triangle blocks
#define FULL_IT 7
#define TAIL  208

// ---------------- device scratch (zero-initialized at module load) ----------------
__device__ __align__(16) int g_cols[NROWS * CAP];
__device__ int   g_cnt [NROWS];     // degree counters (zeroed by k_zero)
__device__ float g_dinv[NROWS];     // finalized in k_mutual
__device__ float g_pew2[P];
__device__ float g_den [NROWS];
__device__ float g_num [NROWS];
__device__ float g_out1[NROWS];
__device__ float g_vec [NROWS];

// ---------------- K0: zero accumulators + counters ----------------
__global__ void k_zero() {
    int i = blockIdx.x * 256 + threadIdx.x;
    if (i < NROWS) { g_den[i] = 0.f; g_num[i] = 0.f; g_out1[i] = 0.f; g_cnt[i] = 0; }
}

__device__ __forceinline__ uint4 ldcs4(const uint4* p) { return __ldcs(p); }

// ---------------- full-row scan (attention blocks only) ----------------
__device__ __forceinline__ void scan_row_full(const uint4* __restrict__ row,
                                              int* cols, int* s_cnt) {
    int tid = threadIdx.x;
    uint4 v[FULL_IT];
    #pragma unroll
    for (int k = 0; k < FULL_IT; k++) v[k] = ldcs4(row + tid + 256 * k);
    uint4 t = make_uint4(0u, 0u, 0u, 0u);
    if (tid < TAIL) t = ldcs4(row + 1792 + tid);

    unsigned orr = t.x | t.y | t.z | t.w;
    #pragma unroll
    for (int k = 0; k < FULL_IT; k++) orr |= v[k].x | v[k].y | v[k].z | v[k].w;

    if (orr) {
        #pragma unroll
        for (int k = 0; k < FULL_IT; k++) {
            int base = 4 * (tid + 256 * k);
            if (v[k].x) { int s = atomicAdd(s_cnt, 1); if (s < CAP) cols[s] = base;     }
            if (v[k].y) { int s = atomicAdd(s_cnt, 1); if (s < CAP) cols[s] = base + 1; }
            if (v[k].z) { int s = atomicAdd(s_cnt, 1); if (s < CAP) cols[s] = base + 2; }
            if (v[k].w) { int s = atomicAdd(s_cnt, 1); if (s < CAP) cols[s] = base + 3; }
        }
        int base = 4 * (1792 + tid);
        if (t.x) { int s = atomicAdd(s_cnt, 1); if (s < CAP) cols[s] = base;     }
        if (t.y) { int s = atomicAdd(s_cnt, 1); if (s < CAP) cols[s] = base + 1; }
        if (t.z) { int s = atomicAdd(s_cnt, 1); if (s < CAP) cols[s] = base + 2; }
        if (t.w) { int s = atomicAdd(s_cnt, 1); if (s < CAP) cols[s] = base + 3; }
    }
}

// ---------------- element append: own shared list + mirror to row c --------------
__device__ __forceinline__ void tri_elem(int c, int rowid, int* s_cnt, int* s_list) {
    if (c < rowid) return;                     // below diagonal of this segment
    int s = atomicAdd(s_cnt, 1);
    if (s < CAP) s_list[s] = c;
    if (c > rowid) {                           // mirror into row c's global list
        int m = atomicAdd(&g_cnt[c], 1);
        if (m < CAP) g_cols[(size_t)c * CAP + m] = rowid;
    }
}

// ---------------- K1: fused pass — paired-row triangle scan + attention ----------
__global__ void __launch_bounds__(256, 6)
k_fused(const float* __restrict__ adj,
        const float* __restrict__ emb,
        const float* __restrict__ w_att,
        const float* __restrict__ b_att,
        const float* __restrict__ w_weight,
        const int*   __restrict__ pos_idx) {
    __shared__ int s_cnt;
    int tid = threadIdx.x;

    if (blockIdx.x >= P) {
        // -------- paired triangle rows: r (top) + rp (bottom), ~2001 uint4 total ----
        __shared__ int s_cnt0, s_cnt1, s_b0, s_b1;
        __shared__ int s_list0[CAP], s_list1[CAP];
        int b  = blockIdx.x - P;
        int r  = b;
        int rp = NROWS - 1 - b;
        int r4  = r >> 2,  rp4 = rp >> 2;
        int L1  = NV4 - r4, L2 = NV4 - rp4;
        int Lt  = L1 + L2;                      // 2001 or 2002 <= 2048
        if (tid == 0) { s_cnt0 = 0; s_cnt1 = 0; }
        __syncthreads();

        const uint4* p0 = (const uint4*)(adj + (size_t)r  * NROWS) + r4;
        const uint4* p1 = (const uint4*)(adj + (size_t)rp * NROWS) + rp4 - L1;  // p1[i] valid for i>=L1

        // 7 unconditional + 1 predicated batched loads (same shape as the R10 scan)
        uint4 v[8];
        unsigned orr = 0;
        #pragma unroll
        for (int k = 0; k < 7; k++) {
            int i = tid + 256 * k;
            v[k] = ldcs4(i < L1 ? p0 + i : p1 + i);
            orr |= v[k].x | v[k].y | v[k].z | v[k].w;
        }
        {
            int i = tid + 1792;
            v[7] = make_uint4(0u, 0u, 0u, 0u);
            if (i < Lt) v[7] = ldcs4(i < L1 ? p0 + i : p1 + i);
            orr |= v[7].x | v[7].y | v[7].z | v[7].w;
        }

        if (orr) {  // rare hit path
            #pragma unroll
            for (int k = 0; k < 8; k++) {
                if (!(v[k].x | v[k].y | v[k].z | v[k].w)) continue;
                int i = tid + 256 * k;
                bool top = (i < L1);
                int rowid = top ? r : rp;
                int c0    = top ? 4 * (r4 + i) : 4 * (rp4 + (i - L1));
                int* cnt  = top ? &s_cnt0 : &s_cnt1;
                int* lst  = top ? s_list0 : s_list1;
                if (v[k].x) tri_elem(c0,     rowid, cnt, lst);
                if (v[k].y) tri_elem(c0 + 1, rowid, cnt, lst);
                if (v[k].z) tri_elem(c0 + 2, rowid, cnt, lst);
                if (v[k].w) tri_elem(c0 + 3, rowid, cnt, lst);
            }
        }
        __syncthreads();
        int c0n = min(s_cnt0, CAP), c1n = min(s_cnt1, CAP);
        if (tid == 0) s_b0 = atomicAdd(&g_cnt[r],  c0n);
        if (tid == 1) s_b1 = atomicAdd(&g_cnt[rp], c1n);
        __syncthreads();
        for (int i = tid; i < c0n; i += 256) {
            int slot = s_b0 + i;
            if (slot < CAP) g_cols[(size_t)r * CAP + slot] = s_list0[i];
        }
        for (int i = tid; i < c1n; i += 256) {
            int slot = s_b1 + i;
            if (slot < CAP) g_cols[(size_t)rp * CAP + slot] = s_list1[i];
        }
        return;
    }

    // -------- attention block for positive p (private full-row scan) --------
    __shared__ int   s_cols[CAP];
    __shared__ __align__(16) float s_emb[D];
    __shared__ __align__(16) float s_proj[D];
    __shared__ float s_red[8];

    int p = blockIdx.x;
    int r = pos_idx[p];
    if (tid == 0) s_cnt = 0;
    __syncthreads();
    scan_row_full((const uint4*)(adj + (size_t)r * NROWS), s_cols, &s_cnt);

    s_emb[tid] = emb[(size_t)r * D + tid];
    __syncthreads();

    int   deg    = min(s_cnt, CAP);
    float dinv_r = rsqrtf((float)s_cnt);
    bool  first  = (p == 0) || (pos_idx[p - 1] != r);  // one-hot SET semantics

    // proj[d] = dot(w_att[d,:], emb_r) + b_att[d]
    {
        const float4* wrow = (const float4*)(w_att + (size_t)tid * D);
        const float4* e4   = (const float4*)s_emb;
        float acc = b_att[tid];
        #pragma unroll 8
        for (int q = 0; q < D / 4; q++) {
            float4 w = wrow[q]; float4 e = e4[q];
            acc += w.x * e.x + w.y * e.y + w.z * e.z + w.w * e.w;
        }
        s_proj[tid] = acc;
    }

    // pew2[p] = dot(emb_r, w_weight[D:2D])
    int warp = tid >> 5, lane = tid & 31;
    {
        float v = s_emb[tid] * w_weight[D + tid];
        #pragma unroll
        for (int o = 16; o > 0; o >>= 1) v += __shfl_xor_sync(0xffffffff, v, o);
        if (lane == 0) s_red[warp] = v;
    }
    __syncthreads();
    float pw2 = s_red[0] + s_red[1] + s_red[2] + s_red[3]
              + s_red[4] + s_red[5] + s_red[6] + s_red[7];
    if (tid == 0) g_pew2[p] = pw2;

    // pair dots: warp per neighbor
    const float4* pr4 = (const float4*)s_proj;
    for (int t = warp; t < deg; t += 8) {
        int j = s_cols[t];
        const float4* ej = (const float4*)(emb + (size_t)j * D);
        float acc = 0.f;
        #pragma unroll
        for (int q = lane; q < D / 4; q += 32) {
            float4 e = ej[q]; float4 pp = pr4[q];
            acc += e.x * pp.x + e.y * pp.y + e.z * pp.z + e.w * pp.w;
        }
        #pragma unroll
        for (int o = 16; o > 0; o >>= 1) acc += __shfl_xor_sync(0xffffffff, acc, o);
        if (lane == 0) {
            float e = expm1f(acc);
            atomicAdd(&g_den[j], e);
            atomicAdd(&g_num[j], e * pw2);
            if (first) atomicAdd(&g_out1[j], dinv_r);
        }
    }
}

// ---------------- K2: mutual weight + reweight (finalizes dinv) ----------------
__global__ void k_mutual(const float* __restrict__ emb,
                         const float* __restrict__ w_weight) {
    __shared__ float s_c0p[4];
    __shared__ float s_c0;
    int tid = threadIdx.x, warp = tid >> 5, lane = tid & 31;

    if (tid < P) {
        float v = g_pew2[tid];
        #pragma unroll
        for (int o = 16; o > 0; o >>= 1) v += __shfl_xor_sync(0xffffffff, v, o);
        if (lane == 0) s_c0p[warp] = v;
    }
    __syncthreads();
    if (tid == 0) s_c0 = s_c0p[0] + s_c0p[1] + s_c0p[2] + s_c0p[3];
    __syncthreads();
    float C0 = s_c0;

    int j = blockIdx.x * 8 + warp;
    if (j >= NROWS) return;
    const float4* ej = (const float4*)(emb + (size_t)j * D);
    const float4* w1 = (const float4*)w_weight;
    float acc = 0.f;
    #pragma unroll
    for (int q = lane; q < D / 4; q += 32) {
        float4 e = ej[q]; float4 w = w1[q];
        acc += e.x * w.x + e.y * w.y + e.z * w.z + e.w * w.w;
    }
    #pragma unroll
    for (int o = 16; o > 0; o >>= 1) acc += __shfl_xor_sync(0xffffffff, acc, o);
    if (lane == 0) {
        float dv = rsqrtf((float)g_cnt[j]);    // deg final after k_fused; deg >= 1
        g_dinv[j] = dv;
        float ctx = (C0 + g_num[j]) / ((float)P + g_den[j]);
        float mw  = 1.0f / (1.0f + expf(-(acc + ctx)));
        g_vec[j] = dv * g_out1[j] * mw;
    }
}

// ---------------- K3: vectorized gather ----------------
__global__ void k_final(float* __restrict__ out, const float* __restrict__ w_final) {
    int j = blockIdx.x * 8 + (threadIdx.x >> 5);
    int lane = threadIdx.x & 31;
    if (j >= NROWS) return;
    int deg = min(g_cnt[j], CAP);
    const int4* cols4 = (const int4*)(g_cols + (size_t)j * CAP);
    int nq = (deg + 3) >> 2;
    float acc = 0.f;
    for (int t = lane; t < nq; t += 32) {
        int4 c = cols4[t];
        int base = t * 4;
        float a0 = (base     < deg) ? g_vec[c.x] : 0.f;
        float a1 = (base + 1 < deg) ? g_vec[c.y] : 0.f;
        float a2 = (base + 2 < deg) ? g_vec[c.z] : 0.f;
        float a3 = (base + 3 < deg) ? g_vec[c.w] : 0.f;
        acc += (a0 + a1) + (a2 + a3);
    }
    #pragma unroll
    for (int o = 16; o > 0; o >>= 1) acc += __shfl_xor_sync(0xffffffff, acc, o);
    if (lane == 0) out[j] = g_dinv[j] * acc * w_final[0];
}

// ---------------- launch ----------------
extern "C" void kernel_launch(void* const* d_in, const int* in_sizes, int n_in,
                              void* d_out, int out_size) {
    const float* adj      = (const float*)d_in[0];
    const float* emb      = (const float*)d_in[1];
    const float* w_att    = (const float*)d_in[2];
    const float* b_att    = (const float*)d_in[3];
    const float* w_weight = (const float*)d_in[4];
    const float* w_final  = (const float*)d_in[5];
    const int*   pos_idx  = (const int*)  d_in[6];
    float* out = (float*)d_out;

    k_zero  <<<(NROWS + 255) / 256, 256>>>();
    k_fused <<<NTRI + P, 256>>>(adj, emb, w_att, b_att, w_weight, pos_idx);
    k_mutual<<<NROWS / 8, 256>>>(emb, w_weight);
    k_final <<<NROWS / 8, 256>>>(out, w_final);
}

// round 15
// speedup vs baseline: 1.5273x; 1.5273x over previous
#include <cuda_runtime.h>
#include <cuda_bf16.h>
#include <math.h>

#define NROWS 8000
#define D     256
#define P     128
#define CAP   192       // max nnz/row; 192*4B = 768B (16B-aligned rows)
#define FULL_IT 7       // 7*256 = 1792 unconditional uint4 loads per block
#define TAIL  208       // 2000 - 1792

// ---------------- device scratch (zero-initialized at module load) ----------------
__device__ __align__(16) int g_cols[NROWS * CAP];
__device__ int   g_deg [NROWS];
__device__ float g_dinv[NROWS];
__device__ float g_pew2[P];
__device__ float g_den [NROWS];   // accumulators: consumed by k_mutual, re-zeroed by k_final
__device__ float g_num [NROWS];
__device__ float g_out1[NROWS];
__device__ float g_vec [NROWS];

// ---------------- lean row scan: batched streaming loads + OR-tree + rare hit path
__device__ __forceinline__ uint4 ldcs4(const uint4* p) {
    return __ldcs(p);   // evict-first: adj is read exactly once
}

__device__ __forceinline__ void scan_row(const uint4* __restrict__ row,
                                         int* cols, int* s_cnt) {
    int tid = threadIdx.x;
    uint4 v[FULL_IT];
    #pragma unroll
    for (int k = 0; k < FULL_IT; k++) v[k] = ldcs4(row + tid + 256 * k);
    uint4 t = make_uint4(0u, 0u, 0u, 0u);
    if (tid < TAIL) t = ldcs4(row + 1792 + tid);

    unsigned orr = t.x | t.y | t.z | t.w;
    #pragma unroll
    for (int k = 0; k < FULL_IT; k++) orr |= v[k].x | v[k].y | v[k].z | v[k].w;

    if (orr) {  // rare: ~5-6% of threads
        #pragma unroll
        for (int k = 0; k < FULL_IT; k++) {
            int base = 4 * (tid + 256 * k);
            if (v[k].x) { int s = atomicAdd(s_cnt, 1); if (s < CAP) cols[s] = base;     }
            if (v[k].y) { int s = atomicAdd(s_cnt, 1); if (s < CAP) cols[s] = base + 1; }
            if (v[k].z) { int s = atomicAdd(s_cnt, 1); if (s < CAP) cols[s] = base + 2; }
            if (v[k].w) { int s = atomicAdd(s_cnt, 1); if (s < CAP) cols[s] = base + 3; }
        }
        int base = 4 * (1792 + tid);
        if (t.x) { int s = atomicAdd(s_cnt, 1); if (s < CAP) cols[s] = base;     }
        if (t.y) { int s = atomicAdd(s_cnt, 1); if (s < CAP) cols[s] = base + 1; }
        if (t.z) { int s = atomicAdd(s_cnt, 1); if (s < CAP) cols[s] = base + 2; }
        if (t.w) { int s = atomicAdd(s_cnt, 1); if (s < CAP) cols[s] = base + 3; }
    }
}

// ---------------- K1: fused big pass (6 blocks/SM) ----------------
__global__ void __launch_bounds__(256, 6)
k_fused(const float* __restrict__ adj,
        const float* __restrict__ emb,
        const float* __restrict__ w_att,
        const float* __restrict__ b_att,
        const float* __restrict__ w_weight,
        const int*   __restrict__ pos_idx) {
    __shared__ int s_cnt;
    int tid = threadIdx.x;

    if (blockIdx.x >= P) {
        int r = blockIdx.x - P;
        if (tid == 0) s_cnt = 0;
        __syncthreads();
        scan_row((const uint4*)(adj + (size_t)r * NROWS), g_cols + (size_t)r * CAP, &s_cnt);
        __syncthreads();
        if (tid == 0) {
            g_deg[r]  = min(s_cnt, CAP);
            g_dinv[r] = rsqrtf((float)s_cnt);   // deg >= 1 (self-loop)
        }
        return;
    }

    // -------- attention block for positive p --------
    __shared__ int   s_cols[CAP];
    __shared__ __align__(16) float s_emb[D];
    __shared__ __align__(16) float s_proj[D];
    __shared__ float s_red[8];

    int p = blockIdx.x;
    int r = pos_idx[p];
    if (tid == 0) s_cnt = 0;
    __syncthreads();
    scan_row((const uint4*)(adj + (size_t)r * NROWS), s_cols, &s_cnt);

    s_emb[tid] = emb[(size_t)r * D + tid];
    __syncthreads();

    int   deg    = min(s_cnt, CAP);
    float dinv_r = rsqrtf((float)s_cnt);
    bool  first  = (p == 0) || (pos_idx[p - 1] != r);  // one-hot SET semantics

    // proj[d] = dot(w_att[d,:], emb_r) + b_att[d]
    {
        const float4* wrow = (const float4*)(w_att + (size_t)tid * D);
        const float4* e4   = (const float4*)s_emb;
        float acc = b_att[tid];
        #pragma unroll 8
        for (int q = 0; q < D / 4; q++) {
            float4 w = wrow[q]; float4 e = e4[q];
            acc += w.x * e.x + w.y * e.y + w.z * e.z + w.w * e.w;
        }
        s_proj[tid] = acc;
    }

    // pew2[p] = dot(emb_r, w_weight[D:2D])
    int warp = tid >> 5, lane = tid & 31;
    {
        float v = s_emb[tid] * w_weight[D + tid];
        #pragma unroll
        for (int o = 16; o > 0; o >>= 1) v += __shfl_xor_sync(0xffffffff, v, o);
        if (lane == 0) s_red[warp] = v;
    }
    __syncthreads();
    float pw2 = s_red[0] + s_red[1] + s_red[2] + s_red[3]
              + s_red[4] + s_red[5] + s_red[6] + s_red[7];
    if (tid == 0) g_pew2[p] = pw2;

    // pair dots: warp per neighbor
    const float4* pr4 = (const float4*)s_proj;
    for (int t = warp; t < deg; t += 8) {
        int j = s_cols[t];
        const float4* ej = (const float4*)(emb + (size_t)j * D);
        float acc = 0.f;
        #pragma unroll
        for (int q = lane; q < D / 4; q += 32) {
            float4 e = ej[q]; float4 pp = pr4[q];
            acc += e.x * pp.x + e.y * pp.y + e.z * pp.z + e.w * pp.w;
        }
        #pragma unroll
        for (int o = 16; o > 0; o >>= 1) acc += __shfl_xor_sync(0xffffffff, acc, o);
        if (lane == 0) {
            float e = expm1f(acc);            // exp(score) - exp(0)
            atomicAdd(&g_den[j], e);
            atomicAdd(&g_num[j], e * pw2);
            if (first) atomicAdd(&g_out1[j], dinv_r);
        }
    }
}

// ---------------- K2: mutual weight + reweight (reads accumulators) ----------------
__global__ void k_mutual(const float* __restrict__ emb,
                         const float* __restrict__ w_weight) {
    __shared__ float s_c0p[4];
    __shared__ float s_c0;
    int tid = threadIdx.x, warp = tid >> 5, lane = tid & 31;

    if (tid < P) {
        float v = g_pew2[tid];
        #pragma unroll
        for (int o = 16; o > 0; o >>= 1) v += __shfl_xor_sync(0xffffffff, v, o);
        if (lane == 0) s_c0p[warp] = v;
    }
    __syncthreads();
    if (tid == 0) s_c0 = s_c0p[0] + s_c0p[1] + s_c0p[2] + s_c0p[3];
    __syncthreads();
    float C0 = s_c0;

    int j = blockIdx.x * 8 + warp;
    if (j >= NROWS) return;
    const float4* ej = (const float4*)(emb + (size_t)j * D);
    const float4* w1 = (const float4*)w_weight;
    float acc = 0.f;
    #pragma unroll
    for (int q = lane; q < D / 4; q += 32) {
        float4 e = ej[q]; float4 w = w1[q];
        acc += e.x * w.x + e.y * w.y + e.z * w.z + e.w * w.w;
    }
    #pragma unroll
    for (int o = 16; o > 0; o >>= 1) acc += __shfl_xor_sync(0xffffffff, acc, o);
    if (lane == 0) {
        float ctx = (C0 + g_num[j]) / ((float)P + g_den[j]);
        float mw  = 1.0f / (1.0f + expf(-(acc + ctx)));
        g_vec[j] = g_dinv[j] * g_out1[j] * mw;
    }
}

// ---------------- K3: vectorized gather + accumulator reset for next call --------
__global__ void k_final(float* __restrict__ out, const float* __restrict__ w_final) {
    int j = blockIdx.x * 8 + (threadIdx.x >> 5);
    int lane = threadIdx.x & 31;
    if (j >= NROWS) return;
    int deg = g_deg[j];
    const int4* cols4 = (const int4*)(g_cols + (size_t)j * CAP);
    int nq = (deg + 3) >> 2;
    float acc = 0.f;
    for (int t = lane; t < nq; t += 32) {
        int4 c = cols4[t];                 // one LDG.128 -> 4 indices
        int base = t * 4;
        float a0 = (base     < deg) ? g_vec[c.x] : 0.f;
        float a1 = (base + 1 < deg) ? g_vec[c.y] : 0.f;
        float a2 = (base + 2 < deg) ? g_vec[c.z] : 0.f;
        float a3 = (base + 3 < deg) ? g_vec[c.w] : 0.f;
        acc += (a0 + a1) + (a2 + a3);
    }
    // reset accumulators for the next call while gathers are in flight
    // (k_mutual consumed them earlier in this call; module-load init covers call 1)
    if (lane == 1) g_den [j] = 0.f;
    if (lane == 2) g_num [j] = 0.f;
    if (lane == 3) g_out1[j] = 0.f;
    #pragma unroll
    for (int o = 16; o > 0; o >>= 1) acc += __shfl_xor_sync(0xffffffff, acc, o);
    if (lane == 0) out[j] = g_dinv[j] * acc * w_final[0];
}

// ---------------- launch ----------------
extern "C" void kernel_launch(void* const* d_in, const int* in_sizes, int n_in,
                              void* d_out, int out_size) {
    const float* adj      = (const float*)d_in[0];
    const float* emb      = (const float*)d_in[1];
    const float* w_att    = (const float*)d_in[2];
    const float* b_att    = (const float*)d_in[3];
    const float* w_weight = (const float*)d_in[4];
    const float* w_final  = (const float*)d_in[5];
    const int*   pos_idx  = (const int*)  d_in[6];
    float* out = (float*)d_out;

    k_fused <<<NROWS + P, 256>>>(adj, emb, w_att, b_att, w_weight, pos_idx);
    k_mutual<<<NROWS / 8, 256>>>(emb, w_weight);
    k_final <<<NROWS / 8, 256>>>(out, w_final);
}

// round 16
// speedup vs baseline: 1.5769x; 1.0325x over previous
#include <cuda_runtime.h>
#include <cuda_bf16.h>
#include <math.h>

#define NROWS 8000
#define D     256
#define P     128
#define CAP   192       // max nnz/row; 192*4B = 768B (16B-aligned rows)
#define FULL_IT 7       // 7*256 = 1792 unconditional uint4 loads per block
#define TAIL  208       // 2000 - 1792

// ---------------- device scratch (zero-initialized at module load) ----------------
__device__ __align__(16) int g_cols[NROWS * CAP];
__device__ int   g_deg [NROWS];
__device__ float g_dinv[NROWS];
__device__ float g_pew2[P];
__device__ float g_den [NROWS];   // consumed by k_mutual, re-zeroed by k_final
__device__ float g_num [NROWS];
__device__ float g_out1[NROWS];
__device__ float g_vec [NROWS];

// ---------------- PDL primitives ----------------
__device__ __forceinline__ void pdl_trigger() {
    asm volatile("griddepcontrol.launch_dependents;");
}
__device__ __forceinline__ void pdl_wait() {
    asm volatile("griddepcontrol.wait;" ::: "memory");
}

// ---------------- lean row scan ----------------
__device__ __forceinline__ uint4 ldcs4(const uint4* p) {
    return __ldcs(p);   // evict-first: adj is read exactly once
}

__device__ __forceinline__ void scan_row(const uint4* __restrict__ row,
                                         int* cols, int* s_cnt) {
    int tid = threadIdx.x;
    uint4 v[FULL_IT];
    #pragma unroll
    for (int k = 0; k < FULL_IT; k++) v[k] = ldcs4(row + tid + 256 * k);
    uint4 t = make_uint4(0u, 0u, 0u, 0u);
    if (tid < TAIL) t = ldcs4(row + 1792 + tid);

    unsigned orr = t.x | t.y | t.z | t.w;
    #pragma unroll
    for (int k = 0; k < FULL_IT; k++) orr |= v[k].x | v[k].y | v[k].z | v[k].w;

    if (orr) {  // rare: ~5-6% of threads
        #pragma unroll
        for (int k = 0; k < FULL_IT; k++) {
            int base = 4 * (tid + 256 * k);
            if (v[k].x) { int s = atomicAdd(s_cnt, 1); if (s < CAP) cols[s] = base;     }
            if (v[k].y) { int s = atomicAdd(s_cnt, 1); if (s < CAP) cols[s] = base + 1; }
            if (v[k].z) { int s = atomicAdd(s_cnt, 1); if (s < CAP) cols[s] = base + 2; }
            if (v[k].w) { int s = atomicAdd(s_cnt, 1); if (s < CAP) cols[s] = base + 3; }
        }
        int base = 4 * (1792 + tid);
        if (t.x) { int s = atomicAdd(s_cnt, 1); if (s < CAP) cols[s] = base;     }
        if (t.y) { int s = atomicAdd(s_cnt, 1); if (s < CAP) cols[s] = base + 1; }
        if (t.z) { int s = atomicAdd(s_cnt, 1); if (s < CAP) cols[s] = base + 2; }
        if (t.w) { int s = atomicAdd(s_cnt, 1); if (s < CAP) cols[s] = base + 3; }
    }
}

// ---------------- K1: fused big pass (6 blocks/SM) ----------------
__global__ void __launch_bounds__(256, 6)
k_fused(const float* __restrict__ adj,
        const float* __restrict__ emb,
        const float* __restrict__ w_att,
        const float* __restrict__ b_att,
        const float* __restrict__ w_weight,
        const int*   __restrict__ pos_idx) {
    __shared__ int s_cnt;
    int tid = threadIdx.x;

    // allow dependents to dispatch once every block has launched (tail overlap)
    pdl_trigger();

    if (blockIdx.x >= P) {
        int r = blockIdx.x - P;
        if (tid == 0) s_cnt = 0;
        __syncthreads();
        scan_row((const uint4*)(adj + (size_t)r * NROWS), g_cols + (size_t)r * CAP, &s_cnt);
        __syncthreads();
        if (tid == 0) {
            g_deg[r]  = min(s_cnt, CAP);
            g_dinv[r] = rsqrtf((float)s_cnt);   // deg >= 1 (self-loop)
        }
        return;
    }

    // -------- attention block for positive p --------
    __shared__ int   s_cols[CAP];
    __shared__ __align__(16) float s_emb[D];
    __shared__ __align__(16) float s_proj[D];
    __shared__ float s_red[8];

    int p = blockIdx.x;
    int r = pos_idx[p];
    if (tid == 0) s_cnt = 0;
    __syncthreads();
    scan_row((const uint4*)(adj + (size_t)r * NROWS), s_cols, &s_cnt);

    s_emb[tid] = emb[(size_t)r * D + tid];
    __syncthreads();

    int   deg    = min(s_cnt, CAP);
    float dinv_r = rsqrtf((float)s_cnt);
    bool  first  = (p == 0) || (pos_idx[p - 1] != r);  // one-hot SET semantics

    // proj[d] = dot(w_att[d,:], emb_r) + b_att[d]
    {
        const float4* wrow = (const float4*)(w_att + (size_t)tid * D);
        const float4* e4   = (const float4*)s_emb;
        float acc = b_att[tid];
        #pragma unroll 8
        for (int q = 0; q < D / 4; q++) {
            float4 w = wrow[q]; float4 e = e4[q];
            acc += w.x * e.x + w.y * e.y + w.z * e.z + w.w * e.w;
        }
        s_proj[tid] = acc;
    }

    // pew2[p] = dot(emb_r, w_weight[D:2D])
    int warp = tid >> 5, lane = tid & 31;
    {
        float v = s_emb[tid] * w_weight[D + tid];
        #pragma unroll
        for (int o = 16; o > 0; o >>= 1) v += __shfl_xor_sync(0xffffffff, v, o);
        if (lane == 0) s_red[warp] = v;
    }
    __syncthreads();
    float pw2 = s_red[0] + s_red[1] + s_red[2] + s_red[3]
              + s_red[4] + s_red[5] + s_red[6] + s_red[7];
    if (tid == 0) g_pew2[p] = pw2;

    // pair dots: warp per neighbor
    const float4* pr4 = (const float4*)s_proj;
    for (int t = warp; t < deg; t += 8) {
        int j = s_cols[t];
        const float4* ej = (const float4*)(emb + (size_t)j * D);
        float acc = 0.f;
        #pragma unroll
        for (int q = lane; q < D / 4; q += 32) {
            float4 e = ej[q]; float4 pp = pr4[q];
            acc += e.x * pp.x + e.y * pp.y + e.z * pp.z + e.w * pp.w;
        }
        #pragma unroll
        for (int o = 16; o > 0; o >>= 1) acc += __shfl_xor_sync(0xffffffff, acc, o);
        if (lane == 0) {
            float e = expm1f(acc);            // exp(score) - exp(0)
            atomicAdd(&g_den[j], e);
            atomicAdd(&g_num[j], e * pw2);
            if (first) atomicAdd(&g_out1[j], dinv_r);
        }
    }
}

// ---------------- K2 (PDL): independent dot first, then wait, then combine -------
__global__ void k_mutual(const float* __restrict__ emb,
                         const float* __restrict__ w_weight) {
    pdl_trigger();   // let k_final dispatch into our tail as well
    __shared__ float s_c0p[4];
    __shared__ float s_c0;
    int tid = threadIdx.x, warp = tid >> 5, lane = tid & 31;

    // ---- phase A (independent of k_fused): emb[j] . w_weight[0:D] ----
    int j = blockIdx.x * 8 + warp;
    float acc = 0.f;
    if (j < NROWS) {
        const float4* ej = (const float4*)(emb + (size_t)j * D);
        const float4* w1 = (const float4*)w_weight;
        #pragma unroll
        for (int q = lane; q < D / 4; q += 32) {
            float4 e = ej[q]; float4 w = w1[q];
            acc += e.x * w.x + e.y * w.y + e.z * w.z + e.w * w.w;
        }
        #pragma unroll
        for (int o = 16; o > 0; o >>= 1) acc += __shfl_xor_sync(0xffffffff, acc, o);
    }

    // ---- wait for k_fused completion (accumulators + dinv + pew2 valid) ----
    pdl_wait();

    if (tid < P) {
        float v = g_pew2[tid];
        #pragma unroll
        for (int o = 16; o > 0; o >>= 1) v += __shfl_xor_sync(0xffffffff, v, o);
        if (lane == 0) s_c0p[warp] = v;
    }
    __syncthreads();
    if (tid == 0) s_c0 = s_c0p[0] + s_c0p[1] + s_c0p[2] + s_c0p[3];
    __syncthreads();
    float C0 = s_c0;

    if (j < NROWS && lane == 0) {
        float ctx = (C0 + g_num[j]) / ((float)P + g_den[j]);
        float mw  = 1.0f / (1.0f + expf(-(acc + ctx)));
        g_vec[j] = g_dinv[j] * g_out1[j] * mw;
    }
}

// ---------------- K3 (PDL): gather + accumulator reset ----------------
__global__ void k_final(float* __restrict__ out, const float* __restrict__ w_final) {
    pdl_wait();      // launch-gap hiding only; all inputs come from k_mutual/k_fused
    int j = blockIdx.x * 8 + (threadIdx.x >> 5);
    int lane = threadIdx.x & 31;
    if (j >= NROWS) return;
    int deg = g_deg[j];
    const int4* cols4 = (const int4*)(g_cols + (size_t)j * CAP);
    int nq = (deg + 3) >> 2;
    float acc = 0.f;
    for (int t = lane; t < nq; t += 32) {
        int4 c = cols4[t];                 // one LDG.128 -> 4 indices
        int base = t * 4;
        float a0 = (base     < deg) ? g_vec[c.x] : 0.f;
        float a1 = (base + 1 < deg) ? g_vec[c.y] : 0.f;
        float a2 = (base + 2 < deg) ? g_vec[c.z] : 0.f;
        float a3 = (base + 3 < deg) ? g_vec[c.w] : 0.f;
        acc += (a0 + a1) + (a2 + a3);
    }
    // reset accumulators for the next call while gathers are in flight
    if (lane == 1) g_den [j] = 0.f;
    if (lane == 2) g_num [j] = 0.f;
    if (lane == 3) g_out1[j] = 0.f;
    #pragma unroll
    for (int o = 16; o > 0; o >>= 1) acc += __shfl_xor_sync(0xffffffff, acc, o);
    if (lane == 0) out[j] = g_dinv[j] * acc * w_final[0];
}

// ---------------- launch: PDL-chained nodes on one stream ----------------
extern "C" void kernel_launch(void* const* d_in, const int* in_sizes, int n_in,
                              void* d_out, int out_size) {
    const float* adj      = (const float*)d_in[0];
    const float* emb      = (const float*)d_in[1];
    const float* w_att    = (const float*)d_in[2];
    const float* b_att    = (const float*)d_in[3];
    const float* w_weight = (const float*)d_in[4];
    const float* w_final  = (const float*)d_in[5];
    const int*   pos_idx  = (const int*)  d_in[6];
    float* out = (float*)d_out;

    k_fused<<<NROWS + P, 256>>>(adj, emb, w_att, b_att, w_weight, pos_idx);

    cudaLaunchAttribute attr[1];
    attr[0].id = cudaLaunchAttributeProgrammaticStreamSerialization;
    attr[0].val.programmaticStreamSerializationAllowed = 1;

    {
        cudaLaunchConfig_t cfg = {};
        cfg.gridDim = dim3(NROWS / 8); cfg.blockDim = dim3(256);
        cfg.stream = 0; cfg.attrs = attr; cfg.numAttrs = 1;
        cudaLaunchKernelEx(&cfg, k_mutual, emb, w_weight);
    }
    {
        cudaLaunchConfig_t cfg = {};
        cfg.gridDim = dim3(NROWS / 8); cfg.blockDim = dim3(256);
        cfg.stream = 0; cfg.attrs = attr; cfg.numAttrs = 1;
        cudaLaunchKernelEx(&cfg, k_final, out, w_final);
    }
}